// round 1
// baseline (speedup 1.0000x reference)
#include <cuda_runtime.h>
#include <cstdint>

// OnlineEmbedding: out[r, :] = table[ids[r], :]
//   ids:   [4096*200] int32 (jax int64 w/o x64 -> int32), values in [0, 1e6)
//   table: [1e6, 64] float32  (row = 256 bytes = 16 float4)
//   out:   [819200, 64] float32
//
// 16 threads per row, one float4 each: gather touches exactly two 128B lines
// per row, store is fully coalesced. Warp = 2 rows -> 32 independent float4
// gathers in flight per warp; grid-wide MLP saturates HBM.

static constexpr int ROWS      = 4096 * 200;   // 819200
static constexpr int EMBED     = 64;
static constexpr int THR_PER_ROW = 16;         // 16 * float4 = 64 floats

__global__ __launch_bounds__(256)
void embed_gather_kernel(const int* __restrict__ ids,
                         const float4* __restrict__ table,
                         float4* __restrict__ out)
{
    int gtid = blockIdx.x * blockDim.x + threadIdx.x;
    int row  = gtid >> 4;           // / THR_PER_ROW
    int lane = gtid & 15;           // float4 index within row
    if (row >= ROWS) return;

    int id = __ldg(&ids[row]);      // broadcast within 16-thread group (L1 hit)

    // table row as float4s: 16 per row
    float4 v = __ldg(&table[(size_t)id * (EMBED / 4) + lane]);
    out[(size_t)row * (EMBED / 4) + lane] = v;
}

extern "C" void kernel_launch(void* const* d_in, const int* in_sizes, int n_in,
                              void* d_out, int out_size)
{
    const int*    ids   = (const int*)d_in[0];
    const float4* table = (const float4*)d_in[1];
    float4*       out   = (float4*)d_out;

    const int total_threads = ROWS * THR_PER_ROW;      // 13,107,200
    const int block = 256;
    const int grid  = (total_threads + block - 1) / block;  // 51200

    embed_gather_kernel<<<grid, block>>>(ids, table, out);
}

// round 2
// speedup vs baseline: 1.2970x; 1.2970x over previous
#include <cuda_runtime.h>
#include <cstdint>

// OnlineEmbedding: out[r, :] = table[ids[r], :]
//   ids:   [819200] int32, values in [0, 1e6)
//   table: [1e6, 64] float32 (row = 256 B = 16 float4)
//   out:   [819200, 64] float32
//
// R1 -> R2: each 16-thread group now handles 4 consecutive rows.
//  - one int4 load grabs 4 ids (1 mem op instead of 4)
//  - 4 independent float4 gathers in flight per thread (MLP x4)
//  - __stcs on output: 210MB write stream is never re-read; evict-first
//    preserves L2 for the table gather.

static constexpr int ROWS        = 4096 * 200;   // 819200
static constexpr int ROWS_PER_GRP = 4;
static constexpr int THR_PER_ROW  = 16;          // 16 * float4 = 64 floats
static constexpr int F4_PER_ROW   = 16;

__global__ __launch_bounds__(256)
void embed_gather_kernel(const int* __restrict__ ids,
                         const float4* __restrict__ table,
                         float4* __restrict__ out)
{
    int gtid = blockIdx.x * blockDim.x + threadIdx.x;
    int grp  = gtid >> 4;            // group of 16 threads
    int lane = gtid & 15;            // float4 index within row
    int row0 = grp * ROWS_PER_GRP;
    if (row0 >= ROWS) return;

    // 4 ids in one streamed vector load (same value across the 16 lanes;
    // HW broadcasts, only one request per group).
    int4 id4 = __ldcs((const int4*)(ids + row0));

    // 4 independent gathers — issue together, overlap DRAM latency.
    float4 v0 = __ldg(table + (size_t)id4.x * F4_PER_ROW + lane);
    float4 v1 = __ldg(table + (size_t)id4.y * F4_PER_ROW + lane);
    float4 v2 = __ldg(table + (size_t)id4.z * F4_PER_ROW + lane);
    float4 v3 = __ldg(table + (size_t)id4.w * F4_PER_ROW + lane);

    float4* o = out + (size_t)row0 * F4_PER_ROW + lane;
    __stcs(o + 0 * F4_PER_ROW, v0);
    __stcs(o + 1 * F4_PER_ROW, v1);
    __stcs(o + 2 * F4_PER_ROW, v2);
    __stcs(o + 3 * F4_PER_ROW, v3);
}

extern "C" void kernel_launch(void* const* d_in, const int* in_sizes, int n_in,
                              void* d_out, int out_size)
{
    const int*    ids   = (const int*)d_in[0];
    const float4* table = (const float4*)d_in[1];
    float4*       out   = (float4*)d_out;

    const int groups        = ROWS / ROWS_PER_GRP;          // 204800
    const int total_threads = groups * THR_PER_ROW;         // 3,276,800
    const int block = 256;
    const int grid  = (total_threads + block - 1) / block;  // 12800

    embed_gather_kernel<<<grid, block>>>(ids, table, out);
}